// round 1
// baseline (speedup 1.0000x reference)
#include <cuda_runtime.h>
#include <math.h>

#define NB 4            // batch
#define S  363          // GRID (sinogram length / recon grid)
#define A  180          // angles
#define W  256          // output size
#define CROP 53         // pad_before

// Scratch: filtered sinogram laid out [n][a][s] (s contiguous)
__device__ float g_filt[NB * A * S];
// cos/sin tables
__device__ float g_cos[A];
__device__ float g_sin[A];

__global__ void init_tables_kernel() {
    int a = threadIdx.x;
    if (a < A) {
        float th = (float)a * (float)(M_PI / 180.0);
        g_cos[a] = cosf(th);
        g_sin[a] = sinf(th);
    }
}

// One block per (n, a) column. Direct spatial ramp-filter convolution:
// out[i] = 0.5*x[i] + sum_{d odd} (-2/(pi*d)^2) * (x[i-d] + x[i+d])
__global__ __launch_bounds__(384) void ramp_filter_kernel(const float* __restrict__ x) {
    const int na = blockIdx.x;
    const int n = na / A;
    const int a = na - n * A;

    __shared__ float xs[S];
    __shared__ float hodd[181];

    const int t = threadIdx.x;
    // Load sinogram column x[n, :, a] (input layout: [n][1][s][a], a fastest)
    for (int s = t; s < S; s += blockDim.x)
        xs[s] = x[(n * S + s) * A + a];
    // Odd-distance filter taps: h(d) = -2 / (pi^2 d^2), d = 2j+1
    for (int j = t; j < 181; j += blockDim.x) {
        float d = 2.0f * (float)j + 1.0f;
        hodd[j] = -2.0f / ((float)(M_PI * M_PI) * d * d);
    }
    __syncthreads();

    if (t < S) {
        float acc = 0.5f * xs[t];
        #pragma unroll 4
        for (int j = 0; j < 181; ++j) {
            const int d = 2 * j + 1;
            float v = 0.0f;
            const int kl = t - d;
            const int kr = t + d;
            if (kl >= 0) v += xs[kl];
            if (kr < S)  v += xs[kr];
            acc = fmaf(v, hodd[j], acc);
        }
        g_filt[(n * A + a) * S + t] = acc;
    }
}

// Backprojection: one block = one output row (256 px) of one batch image.
__global__ __launch_bounds__(256) void backproject_kernel(float* __restrict__ out) {
    const int n  = blockIdx.y;
    const int yy = blockIdx.x;
    const int xx = threadIdx.x;

    __shared__ float sc[A];
    __shared__ float ss[A];
    for (int a = threadIdx.x; a < A; a += blockDim.x) {
        sc[a] = g_cos[a];
        ss[a] = g_sin[a];
    }
    __syncthreads();

    const float step = 2.0f / 362.0f;   // linspace(-1,1,363) step
    const float ux = fmaf((float)(xx + CROP), step, -1.0f);
    const float uy = fmaf((float)(yy + CROP), step, -1.0f);

    const float* __restrict__ fp = g_filt + (size_t)n * A * S;

    float acc = 0.0f;
    #pragma unroll 4
    for (int a = 0; a < A; ++a) {
        const float T   = ux * sc[a] - uy * ss[a];
        const float pos = (T + 1.0f) * 181.0f;     // (S-1)/2 = 181
        const float i0f = floorf(pos);
        const float w   = pos - i0f;
        const int i0 = (int)i0f;
        const int i1 = i0 + 1;
        const int i0c = min(max(i0, 0), S - 1);
        const int i1c = min(max(i1, 0), S - 1);
        const float* row = fp + a * S;
        const float v0 = row[i0c];
        const float v1 = row[i1c];
        const float w0 = (i0 >= 0 && i0 < S) ? (1.0f - w) : 0.0f;
        const float w1 = (i1 >= 0 && i1 < S) ? w          : 0.0f;
        acc = fmaf(v0, w0, fmaf(v1, w1, acc));
    }

    out[((size_t)n * W + yy) * W + xx] = acc * (float)(M_PI / 360.0);
}

extern "C" void kernel_launch(void* const* d_in, const int* in_sizes, int n_in,
                              void* d_out, int out_size) {
    const float* x = (const float*)d_in[0];
    float* out = (float*)d_out;

    init_tables_kernel<<<1, 192>>>();
    ramp_filter_kernel<<<NB * A, 384>>>(x);
    backproject_kernel<<<dim3(W, NB), 256>>>(out);
}

// round 2
// speedup vs baseline: 1.4406x; 1.4406x over previous
#include <cuda_runtime.h>
#include <math.h>

#define NB   4      // batch
#define S    363    // sinogram length / recon grid
#define A    180    // angles
#define W    256    // output size
#define CROP 53     // pad_before
#define RPAD 364    // padded pair-row entries: pairs for i in [-1, 362]

// pair[na][k] = (p[k-1], p[k]) with p[-1] = p[363] = 0  (p = filtered sinogram row)
__device__ float2 g_pairs[NB * A * RPAD];

// One block per (n, a) column. Spatial ramp-filter convolution with zero-padded
// shared buffer (no bounds checks):
// out[i] = 0.5*x[i] + sum_{d odd} (-2/(pi*d)^2) * (x[i-d] + x[i+d])
__global__ __launch_bounds__(384) void ramp_filter_kernel(const float* __restrict__ x) {
    const int na = blockIdx.x;
    const int n  = na / A;
    const int a  = na - n * A;

    __shared__ float xsp[S + 2 * 362];   // [0,362) zeros | [362,725) data | [725,1087) zeros
    __shared__ float hodd[181];

    const int t = threadIdx.x;
    if (t < 362) {
        xsp[t] = 0.0f;
        xsp[725 + t] = 0.0f;
    }
    // input layout: [n][1][s][a], a fastest
    for (int s = t; s < S; s += 384)
        xsp[362 + s] = x[(n * S + s) * A + a];
    if (t < 181) {
        float d = 2.0f * (float)t + 1.0f;
        hodd[t] = -2.0f / ((float)(M_PI * M_PI) * d * d);
    }
    __syncthreads();

    float* gr = (float*)(g_pairs + (size_t)na * RPAD);
    if (t < S) {
        const float* c = xsp + 362 + t;
        float acc = 0.5f * c[0];
        #pragma unroll 4
        for (int j = 0; j < 181; ++j) {
            const int d = 2 * j + 1;
            acc = fmaf(c[-d] + c[d], hodd[j], acc);
        }
        gr[2 * (t + 1)] = acc;   // pair[t+1].x = p[t]
        gr[2 * t + 1]   = acc;   // pair[t].y   = p[t]
    } else if (t == 363) {
        gr[0]           = 0.0f;  // pair[0].x   = p[-1]
        gr[2 * 363 + 1] = 0.0f;  // pair[363].y = p[363]
    }
}

// One block = one output row (256 px) of one batch image. No clamps needed:
// cropped-region positions give i0 in [-1, 362], covered by the padded pairs.
__global__ __launch_bounds__(256) void backproject_kernel(float* __restrict__ out) {
    const int n  = blockIdx.y;
    const int yy = blockIdx.x;
    const int xx = threadIdx.x;

    __shared__ float2 scb[A];    // (181*cos, 181*(1 - uy*sin)) per angle

    const float step = 2.0f / 362.0f;
    const float uy = fmaf((float)(yy + CROP), step, -1.0f);

    if (threadIdx.x < A) {
        float sn, cs;
        sincosf((float)threadIdx.x * (float)(M_PI / 180.0), &sn, &cs);
        scb[threadIdx.x] = make_float2(181.0f * cs, fmaf(-181.0f * uy, sn, 181.0f));
    }
    __syncthreads();

    const float ux = fmaf((float)(xx + CROP), step, -1.0f);
    const float2* __restrict__ row = g_pairs + (size_t)n * A * RPAD + 1;  // +1: i0=-1 -> idx 0

    float acc0 = 0.0f;
    float accw = 0.0f;
    #pragma unroll 4
    for (int a = 0; a < A; ++a, row += RPAD) {
        const float2 cb = scb[a];
        const float pos = fmaf(ux, cb.x, cb.y);   // (T+1)*181
        const float i0f = floorf(pos);
        const float w   = pos - i0f;
        const int   i0  = (int)i0f;               // in [-1, 362]
        const float2 v  = __ldg(row + i0);        // (v0, v1) in one LDG.64
        acc0 += v.x;
        accw = fmaf(w, v.y - v.x, accw);
    }

    out[((size_t)n * W + yy) * W + xx] = (acc0 + accw) * (float)(M_PI / 360.0);
}

extern "C" void kernel_launch(void* const* d_in, const int* in_sizes, int n_in,
                              void* d_out, int out_size) {
    const float* x = (const float*)d_in[0];
    float* out = (float*)d_out;

    ramp_filter_kernel<<<NB * A, 384>>>(x);
    backproject_kernel<<<dim3(W, NB), 256>>>(out);
}

// round 3
// speedup vs baseline: 1.5550x; 1.0794x over previous
#include <cuda_runtime.h>
#include <math.h>

#define NB   4      // batch
#define S    363    // sinogram length / recon grid
#define A    180    // angles
#define W    256    // output size
#define CROP 53     // pad_before
#define RPAD 364    // padded pair-row entries: pairs for i in [-1, 362]

// pair[na][k] = (p[k-1], p[k]) with p[-1] = p[363] = 0  (p = filtered sinogram row)
__device__ float2 g_pairs[NB * A * RPAD];

// One block per (n, a) column. Spatial ramp-filter convolution, taps folded to
// immediates via full unroll:
// out[i] = 0.5*x[i] + sum_{d odd} (-2/(pi*d)^2) * (x[i-d] + x[i+d])
__global__ __launch_bounds__(384) void ramp_filter_kernel(const float* __restrict__ x) {
    const int na = blockIdx.x;
    const int n  = na / A;
    const int a  = na - n * A;

    __shared__ float xsp[S + 2 * 362];   // [0,362) zeros | [362,725) data | [725,1087) zeros

    const int t = threadIdx.x;
    if (t < 362) {
        xsp[t] = 0.0f;
        xsp[725 + t] = 0.0f;
    }
    // input layout: [n][1][s][a], a fastest
    for (int s = t; s < S; s += 384)
        xsp[362 + s] = x[(n * S + s) * A + a];
    __syncthreads();

    float* gr = (float*)(g_pairs + (size_t)na * RPAD);
    if (t < S) {
        const float* c = xsp + 362 + t;
        float acc = 0.5f * c[0];
        #pragma unroll
        for (int j = 0; j < 181; ++j) {
            const int d = 2 * j + 1;
            const float h = -2.0f / ((float)(M_PI * M_PI) * (float)d * (float)d);
            acc = fmaf(c[-d] + c[d], h, acc);
        }
        gr[2 * (t + 1)] = acc;   // pair[t+1].x = p[t]
        gr[2 * t + 1]   = acc;   // pair[t].y   = p[t]
    } else if (t == 363) {
        gr[0]           = 0.0f;  // pair[0].x   = p[-1]
        gr[2 * 363 + 1] = 0.0f;  // pair[363].y = p[363]
    }
}

// One block = one output row (256 px) of one batch image; 128 threads,
// 2 pixels per thread (xx, xx+128) for doubled gather MLP.
__global__ __launch_bounds__(128) void backproject_kernel(float* __restrict__ out) {
    const int n  = blockIdx.y;
    const int yy = blockIdx.x;
    const int xx = threadIdx.x;

    // per angle: (C = 181*cos, B = 181*(1 - uy*sin) + 1, D = 128*cos, pad)
    __shared__ float4 scb[A];

    const float step = 2.0f / 362.0f;
    const float uy = fmaf((float)(yy + CROP), step, -1.0f);

    for (int a = threadIdx.x; a < A; a += 128) {
        float sn, cs;
        sincosf((float)a * (float)(M_PI / 180.0), &sn, &cs);
        scb[a] = make_float4(181.0f * cs,
                             fmaf(-181.0f * uy, sn, 182.0f),
                             128.0f * cs, 0.0f);
    }
    __syncthreads();

    const float ux = fmaf((float)(xx + CROP), step, -1.0f);
    const float2* __restrict__ row = g_pairs + (size_t)n * A * RPAD;

    float acc0a = 0.0f, accwa = 0.0f;
    float acc0b = 0.0f, accwb = 0.0f;

    #pragma unroll 4
    for (int a = 0; a < A; ++a, row += RPAD) {
        const float4 cb = scb[a];
        const float qa = fmaf(ux, cb.x, cb.y);   // (T+1)*181 + 1, in [0.98, 363.02]
        const float qb = qa + cb.z;

        const int ia = (int)qa;                  // trunc == floor (q > 0)
        const int ib = (int)qb;
        const float wa = qa - (float)ia;
        const float wb = qb - (float)ib;

        const float2 va = __ldg(row + ia);       // (p[i-1+..], p[i..]) one LDG.64
        const float2 vb = __ldg(row + ib);

        acc0a += va.x;
        accwa = fmaf(wa, va.y - va.x, accwa);
        acc0b += vb.x;
        accwb = fmaf(wb, vb.y - vb.x, accwb);
    }

    float* o = out + ((size_t)n * W + yy) * W + xx;
    o[0]   = (acc0a + accwa) * (float)(M_PI / 360.0);
    o[128] = (acc0b + accwb) * (float)(M_PI / 360.0);
}

extern "C" void kernel_launch(void* const* d_in, const int* in_sizes, int n_in,
                              void* d_out, int out_size) {
    const float* x = (const float*)d_in[0];
    float* out = (float*)d_out;

    ramp_filter_kernel<<<NB * A, 384>>>(x);
    backproject_kernel<<<dim3(W, NB), 128>>>(out);
}